// round 12
// baseline (speedup 1.0000x reference)
#include <cuda_runtime.h>
#include <math.h>

#define N_NODES_ 100000
#define N_EDGES_ 500000
#define HID_ 128
#define NIN_ 16
#define SCAN_B 1024
#define NBLK_ ((N_NODES_ + SCAN_B - 1) / SCAN_B)   // 98
#define NODE_BLKS ((N_NODES_ + 63) / 64)           // 1563
#define SSTR 132                                   // smem row stride (floats), conflict-free

typedef unsigned int uint32;

// ---- static scratch (no allocations allowed) ----
__device__ float g_h  [N_NODES_ * HID_];
__device__ float g_hn [N_NODES_ * HID_];
__device__ float g_P  [N_NODES_ * 2 * HID_];   // edge-pred node factors; reused as aggr16
__device__ int   g_deg   [N_NODES_];
__device__ int   g_incl  [N_NODES_];
__device__ int   g_rowptr[N_NODES_ + 1];
__device__ int   g_cursor[N_NODES_];
__device__ int   g_bsum  [NBLK_];
__device__ int   g_boff  [NBLK_];
__device__ int   g_csrc  [N_EDGES_];
__device__ float g_cea   [N_EDGES_];

// ---- fragment-ordered BF16 hi/lo weights: [kstep16][ntile][lane] = {bhi0,bhi1,blo0,blo1}
#define WF_W10 0                 // K=16 : 1*16*32   = 512
#define WF_W20 512               // K=128: 8*16*32   = 4096
#define WF_W1  4608              // 4 x 4096
#define WF_W2  20992             // 4 x 4096
#define WF_WPA 37376             // Wp1 rows 0..127
#define WF_WPB 41472             // Wp1 rows 128..255
#define WF_TOTAL 45568
__device__ uint4 g_WF[WF_TOTAL];

__device__ __forceinline__ float4 ld4(const float* p) { return *reinterpret_cast<const float4*>(p); }
__device__ __forceinline__ void st4(float* p, float4 v) { *reinterpret_cast<float4*>(p) = v; }
__device__ __forceinline__ float eluf(float x) { return x > 0.f ? x : expm1f(x); }

// ---- bf16 split helpers ----
// pack2(x0, x1): x0 -> low half, x1 -> high half (cvt d.hi = first src operand)
__device__ __forceinline__ uint32 pack2(float x0, float x1) {
    uint32 r; asm("cvt.rn.bf16x2.f32 %0, %1, %2;" : "=r"(r) : "f"(x1), "f"(x0)); return r;
}
__device__ __forceinline__ float lo_f(uint32 p) { return __uint_as_float(p << 16); }
__device__ __forceinline__ float hi_f(uint32 p) { return __uint_as_float(p & 0xffff0000u); }

// D += A(bf16) * B(bf16), m16n8k16
__device__ __forceinline__ void mma16(float c[4], uint32 a0, uint32 a1, uint32 a2, uint32 a3,
                                      uint32 b0, uint32 b1)
{
    asm volatile(
        "mma.sync.aligned.m16n8k16.row.col.f32.bf16.bf16.f32 "
        "{%0,%1,%2,%3}, {%4,%5,%6,%7}, {%8,%9}, {%0,%1,%2,%3};"
        : "+f"(c[0]), "+f"(c[1]), "+f"(c[2]), "+f"(c[3])
        : "r"(a0), "r"(a1), "r"(a2), "r"(a3), "r"(b0), "r"(b1));
}

// ---------------------------------------------------------------------------
// MMA phase from smem: warp computes C[16 x 128] = Zw @ W, 3xBF16 split.
// ---------------------------------------------------------------------------
template <int KSTEPS16>
__device__ __forceinline__ void mma_phase(const float* Zw, const uint4* __restrict__ WF,
                                          int lane, float c[16][4])
{
    int g = lane >> 2, t = lane & 3;
    #pragma unroll
    for (int nt = 0; nt < 16; nt++) { c[nt][0] = 0.f; c[nt][1] = 0.f; c[nt][2] = 0.f; c[nt][3] = 0.f; }

    #pragma unroll 1
    for (int ks = 0; ks < KSTEPS16; ks++) {
        int kb = ks * 16 + 2 * t;
        float2 za = *(const float2*)&Zw[g * SSTR + kb];
        float2 zb = *(const float2*)&Zw[(g + 8) * SSTR + kb];
        float2 zc = *(const float2*)&Zw[g * SSTR + kb + 8];
        float2 zd = *(const float2*)&Zw[(g + 8) * SSTR + kb + 8];
        uint32 ah0 = pack2(za.x, za.y);
        uint32 ah1 = pack2(zb.x, zb.y);
        uint32 ah2 = pack2(zc.x, zc.y);
        uint32 ah3 = pack2(zd.x, zd.y);
        uint32 al0 = pack2(za.x - lo_f(ah0), za.y - hi_f(ah0));
        uint32 al1 = pack2(zb.x - lo_f(ah1), zb.y - hi_f(ah1));
        uint32 al2 = pack2(zc.x - lo_f(ah2), zc.y - hi_f(ah2));
        uint32 al3 = pack2(zd.x - lo_f(ah3), zd.y - hi_f(ah3));
        const uint4* wrow = &WF[ks * 16 * 32 + lane];
        #pragma unroll
        for (int nt = 0; nt < 16; nt++) {
            uint4 wf = wrow[nt * 32];
            mma16(c[nt], ah0, ah1, ah2, ah3, wf.x, wf.y);   // Ahi*Bhi
            mma16(c[nt], al0, al1, al2, al3, wf.x, wf.y);   // Alo*Bhi
            mma16(c[nt], ah0, ah1, ah2, ah3, wf.z, wf.w);   // Ahi*Blo
        }
    }
}

// ---------------------------------------------------------------------------
// MMA phase from REGISTERS: A = ec[16][4] (phase-1 C fragment after bias+elu).
// C-fragment(g, nt*8+2t / +1; g+8, ...) == A-fragment(k-step ks):
//   a0 = ec[2ks][0..1], a1 = ec[2ks][2..3], a2 = ec[2ks+1][0..1], a3 = ec[2ks+1][2..3].
// Fully unrolled so ec stays statically indexed (register-resident).
// ---------------------------------------------------------------------------
__device__ __forceinline__ void mma_phase_reg(const float ec[16][4],
                                              const uint4* __restrict__ WF,
                                              int lane, float c[16][4])
{
    #pragma unroll
    for (int nt = 0; nt < 16; nt++) { c[nt][0] = 0.f; c[nt][1] = 0.f; c[nt][2] = 0.f; c[nt][3] = 0.f; }

    #pragma unroll
    for (int ks = 0; ks < 8; ks++) {
        uint32 ah0 = pack2(ec[2 * ks][0],     ec[2 * ks][1]);
        uint32 ah1 = pack2(ec[2 * ks][2],     ec[2 * ks][3]);
        uint32 ah2 = pack2(ec[2 * ks + 1][0], ec[2 * ks + 1][1]);
        uint32 ah3 = pack2(ec[2 * ks + 1][2], ec[2 * ks + 1][3]);
        uint32 al0 = pack2(ec[2 * ks][0] - lo_f(ah0),     ec[2 * ks][1] - hi_f(ah0));
        uint32 al1 = pack2(ec[2 * ks][2] - lo_f(ah1),     ec[2 * ks][3] - hi_f(ah1));
        uint32 al2 = pack2(ec[2 * ks + 1][0] - lo_f(ah2), ec[2 * ks + 1][1] - hi_f(ah2));
        uint32 al3 = pack2(ec[2 * ks + 1][2] - lo_f(ah3), ec[2 * ks + 1][3] - hi_f(ah3));
        const uint4* wrow = &WF[ks * 16 * 32 + lane];
        #pragma unroll
        for (int nt = 0; nt < 16; nt++) {
            uint4 wf = wrow[nt * 32];
            mma16(c[nt], ah0, ah1, ah2, ah3, wf.x, wf.y);   // Ahi*Bhi
            mma16(c[nt], al0, al1, al2, al3, wf.x, wf.y);   // Alo*Bhi
            mma16(c[nt], ah0, ah1, ah2, ah3, wf.z, wf.w);   // Ahi*Blo
        }
    }
}

// ---------------------------------------------------------------------------
// Weight fragment prep (once per launch): bf16 hi/lo B-fragments for k16 MMA.
// ---------------------------------------------------------------------------
__global__ void k_wfrag(const float* __restrict__ W10, const float* __restrict__ W20,
                        const float* __restrict__ W1s, const float* __restrict__ W2s,
                        const float* __restrict__ Wp1)
{
    int i = blockIdx.x * 256 + threadIdx.x;
    if (i >= WF_TOTAL) return;
    const float* W; int idx;
    if (i < 512)         { W = W10; idx = i; }
    else if (i < 4608)   { W = W20; idx = i - 512; }
    else if (i < 20992)  { int j = i - 4608;  W = W1s + (j >> 12) * 16384; idx = j & 4095; }
    else if (i < 37376)  { int j = i - 20992; W = W2s + (j >> 12) * 16384; idx = j & 4095; }
    else if (i < 41472)  { W = Wp1;           idx = i - 37376; }
    else                 { W = Wp1 + 16384;   idx = i - 41472; }
    int lane = idx & 31, nt = (idx >> 5) & 15, ks = idx >> 9;
    int t = lane & 3, g = lane >> 2;
    int n  = nt * 8 + g;
    int kb = ks * 16 + 2 * t;
    float w00 = W[kb * 128 + n];
    float w01 = W[(kb + 1) * 128 + n];
    float w10 = W[(kb + 8) * 128 + n];
    float w11 = W[(kb + 9) * 128 + n];
    uint32 h0 = pack2(w00, w01);
    uint32 h1 = pack2(w10, w11);
    uint32 l0 = pack2(w00 - lo_f(h0), w01 - hi_f(h0));
    uint32 l1 = pack2(w10 - lo_f(h1), w11 - hi_f(h1));
    g_WF[i] = make_uint4(h0, h1, l0, l1);
}

// ---------------------------------------------------------------------------
// CSR build (multi-block scan — verified fast path)
// ---------------------------------------------------------------------------
__global__ void k_hist(const int* __restrict__ ei) {
    int e = blockIdx.x * blockDim.x + threadIdx.x;
    if (e < N_EDGES_) atomicAdd(&g_deg[ei[N_EDGES_ + e]], 1);
}

__global__ void k_scanA() {
    __shared__ int s[SCAN_B];
    int t = threadIdx.x;
    int g = blockIdx.x * SCAN_B + t;
    int v = (g < N_NODES_) ? g_deg[g] : 0;
    s[t] = v; __syncthreads();
    for (int d = 1; d < SCAN_B; d <<= 1) {
        int u = (t >= d) ? s[t - d] : 0;
        __syncthreads(); s[t] += u; __syncthreads();
    }
    if (g < N_NODES_) g_incl[g] = s[t];
    if (t == SCAN_B - 1) g_bsum[blockIdx.x] = s[t];
}

__global__ void k_scanB() {
    __shared__ int s[128];
    int t = threadIdx.x;
    int v = (t < NBLK_) ? g_bsum[t] : 0;
    s[t] = v; __syncthreads();
    for (int d = 1; d < 128; d <<= 1) {
        int u = (t >= d) ? s[t - d] : 0;
        __syncthreads(); s[t] += u; __syncthreads();
    }
    if (t < NBLK_) g_boff[t] = s[t] - v;
}

__global__ void k_scanC() {
    int g = blockIdx.x * SCAN_B + threadIdx.x;
    if (g >= N_NODES_) return;
    int ex = g_incl[g] - g_deg[g] + g_boff[blockIdx.x];
    g_rowptr[g] = ex;
    g_cursor[g] = ex;
    if (g == N_NODES_ - 1) g_rowptr[N_NODES_] = g_incl[g] + g_boff[blockIdx.x];
}

__global__ void k_fill(const int* __restrict__ ei, const float* __restrict__ ea) {
    int e = blockIdx.x * blockDim.x + threadIdx.x;
    if (e >= N_EDGES_) return;
    int dst = ei[N_EDGES_ + e];
    int slot = atomicAdd(&g_cursor[dst], 1);
    g_csrc[slot] = ei[e];
    g_cea[slot]  = ea[e];
}

// ---------------------------------------------------------------------------
// Layer-0 aggregation (16 features) via CSR gather
// ---------------------------------------------------------------------------
__global__ void k_aggr0(const float* __restrict__ x, const float* __restrict__ We,
                        const float* __restrict__ be, float* __restrict__ aggr)
{
    int t = blockIdx.x * blockDim.x + threadIdx.x;
    int node = t >> 4;
    int f = t & 15;
    if (node >= N_NODES_) return;
    int beg = g_rowptr[node], end = g_rowptr[node + 1];
    float w = We[f], b = be[f], acc = 0.f;
    for (int p = beg; p < end; p++) {
        float m = x[g_csrc[p] * NIN_ + f] + g_cea[p] * w + b;
        acc += fmaxf(m, 0.f);
    }
    aggr[node * NIN_ + f] = acc;
}

// ---------------------------------------------------------------------------
// Layer-0 node MLP (tensor core): 64 nodes/block, 4 warps x 16 rows.
// Phase 1 -> phase 2 via registers (no smem round-trip).
// ---------------------------------------------------------------------------
__global__ void __launch_bounds__(128)
node_mlp16_tc(const float* __restrict__ xin, const float* __restrict__ aggr,
              const float* __restrict__ b1, const float* __restrict__ b2,
              float* __restrict__ hout)
{
    __shared__ __align__(16) float Z[64 * SSTR];

    int tid = threadIdx.x, w = tid >> 5, lane = tid & 31;
    int nb = blockIdx.x * 64;

    for (int i = tid; i < 64 * 4; i += 128) {
        int row = i >> 2, c4 = i & 3;
        int node = nb + row;
        float4 v = make_float4(0.f, 0.f, 0.f, 0.f);
        if (node < N_NODES_) {
            float4 a = ld4(&xin[node * NIN_ + c4 * 4]);
            float4 g = ld4(&aggr[node * NIN_ + c4 * 4]);
            v = make_float4(a.x + g.x, a.y + g.y, a.z + g.z, a.w + g.w);
        }
        st4(&Z[row * SSTR + c4 * 4], v);
    }
    __syncthreads();

    float c[16][4];
    const float* Zw = &Z[w * 16 * SSTR];
    int g = lane >> 2, t = lane & 3;

    mma_phase<1>(Zw, &g_WF[WF_W10], lane, c);

    // bias + elu in registers -> phase-2 A fragment
    float ec[16][4];
    #pragma unroll
    for (int nt = 0; nt < 16; nt++) {
        int col = nt * 8 + 2 * t;
        float2 bb = *(const float2*)&b1[col];
        ec[nt][0] = eluf(c[nt][0] + bb.x);
        ec[nt][1] = eluf(c[nt][1] + bb.y);
        ec[nt][2] = eluf(c[nt][2] + bb.x);
        ec[nt][3] = eluf(c[nt][3] + bb.y);
    }

    mma_phase_reg(ec, &g_WF[WF_W20], lane, c);
    int n0 = nb + w * 16 + g;
    #pragma unroll
    for (int nt = 0; nt < 16; nt++) {
        int col = nt * 8 + 2 * t;
        float2 bb = *(const float2*)&b2[col];
        float2 e0 = make_float2(eluf(c[nt][0] + bb.x), eluf(c[nt][1] + bb.y));
        float2 e1 = make_float2(eluf(c[nt][2] + bb.x), eluf(c[nt][3] + bb.y));
        if (n0 < N_NODES_)     *(float2*)&hout[n0 * HID_ + col]       = e0;
        if (n0 + 8 < N_NODES_) *(float2*)&hout[(n0 + 8) * HID_ + col] = e1;
    }
}

// ---------------------------------------------------------------------------
// Fused GINE layer: CSR gather + 2 MMA phases (register-chained).
// ---------------------------------------------------------------------------
__global__ void __launch_bounds__(128)
gine_tc(const float* __restrict__ h,
        const float* __restrict__ We, const float* __restrict__ be,
        const uint4* __restrict__ WF1, const float* __restrict__ b1,
        const uint4* __restrict__ WF2, const float* __restrict__ b2,
        float* __restrict__ hout)
{
    __shared__ __align__(16) float Z[64 * SSTR];

    int tid = threadIdx.x, w = tid >> 5, lane = tid & 31;
    int nb = blockIdx.x * 64;

    // gather prologue: each warp fills its 16 rows
    {
        float4 wv = ld4(&We[lane * 4]);
        float4 bg = ld4(&be[lane * 4]);
        for (int n = 0; n < 16; n++) {
            int node = nb + w * 16 + n;
            float4 acc = make_float4(0.f, 0.f, 0.f, 0.f);
            if (node < N_NODES_) {
                acc = ld4(&h[node * HID_ + lane * 4]);
                int beg = g_rowptr[node], end = g_rowptr[node + 1];
                for (int p = beg; p < end; p++) {
                    int s = g_csrc[p];
                    float we = g_cea[p];
                    float4 hv = ld4(&h[s * HID_ + lane * 4]);
                    acc.x += fmaxf(fmaf(we, wv.x, hv.x) + bg.x, 0.f);
                    acc.y += fmaxf(fmaf(we, wv.y, hv.y) + bg.y, 0.f);
                    acc.z += fmaxf(fmaf(we, wv.z, hv.z) + bg.z, 0.f);
                    acc.w += fmaxf(fmaf(we, wv.w, hv.w) + bg.w, 0.f);
                }
            }
            st4(&Z[(w * 16 + n) * SSTR + lane * 4], acc);
        }
    }
    __syncwarp();

    float c[16][4];
    const float* Zw = &Z[w * 16 * SSTR];
    int g = lane >> 2, t = lane & 3;

    mma_phase<8>(Zw, WF1, lane, c);

    // bias + elu in registers -> phase-2 A fragment
    float ec[16][4];
    #pragma unroll
    for (int nt = 0; nt < 16; nt++) {
        int col = nt * 8 + 2 * t;
        float2 bb = *(const float2*)&b1[col];
        ec[nt][0] = eluf(c[nt][0] + bb.x);
        ec[nt][1] = eluf(c[nt][1] + bb.y);
        ec[nt][2] = eluf(c[nt][2] + bb.x);
        ec[nt][3] = eluf(c[nt][3] + bb.y);
    }

    mma_phase_reg(ec, WF2, lane, c);
    int n0 = nb + w * 16 + g;
    #pragma unroll
    for (int nt = 0; nt < 16; nt++) {
        int col = nt * 8 + 2 * t;
        float2 bb = *(const float2*)&b2[col];
        float2 e0 = make_float2(eluf(c[nt][0] + bb.x), eluf(c[nt][1] + bb.y));
        float2 e1 = make_float2(eluf(c[nt][2] + bb.x), eluf(c[nt][3] + bb.y));
        if (n0 < N_NODES_)     *(float2*)&hout[n0 * HID_ + col]       = e0;
        if (n0 + 8 < N_NODES_) *(float2*)&hout[(n0 + 8) * HID_ + col] = e1;
    }
}

// ---------------------------------------------------------------------------
// Edge-predictor node factors. 64 nodes/block, 4 warps x 16 rows.
// ---------------------------------------------------------------------------
__global__ void __launch_bounds__(128)
k_prednode_tc(const float* __restrict__ h, float* __restrict__ P)
{
    __shared__ __align__(16) float Z[64 * SSTR];

    int tid = threadIdx.x, w = tid >> 5, lane = tid & 31;
    int nb = blockIdx.x * 64;

    for (int i = tid; i < 64 * 32; i += 128) {
        int row = i >> 5, c4 = i & 31;
        int node = nb + row;
        float4 v = make_float4(0.f, 0.f, 0.f, 0.f);
        if (node < N_NODES_) v = ld4(&h[node * HID_ + c4 * 4]);
        st4(&Z[row * SSTR + c4 * 4], v);
    }
    __syncthreads();

    float c[16][4];
    const float* Zw = &Z[w * 16 * SSTR];
    int g = lane >> 2, t = lane & 3;
    int n0 = nb + w * 16 + g;

    mma_phase<8>(Zw, &g_WF[WF_WPA], lane, c);
    #pragma unroll
    for (int nt = 0; nt < 16; nt++) {
        int col = nt * 8 + 2 * t;
        if (n0 < N_NODES_)     *(float2*)&P[n0 * 256 + col]       = make_float2(c[nt][0], c[nt][1]);
        if (n0 + 8 < N_NODES_) *(float2*)&P[(n0 + 8) * 256 + col] = make_float2(c[nt][2], c[nt][3]);
    }

    mma_phase<8>(Zw, &g_WF[WF_WPB], lane, c);
    #pragma unroll
    for (int nt = 0; nt < 16; nt++) {
        int col = nt * 8 + 2 * t;
        if (n0 < N_NODES_)     *(float2*)&P[n0 * 256 + 128 + col]       = make_float2(c[nt][0], c[nt][1]);
        if (n0 + 8 < N_NODES_) *(float2*)&P[(n0 + 8) * 256 + 128 + col] = make_float2(c[nt][2], c[nt][3]);
    }
}

// ---------------------------------------------------------------------------
// Per-edge predictor epilogue: out[e] = elu(A[src]+B[dst]+bp1) . Wp2 + bp2
// ---------------------------------------------------------------------------
__global__ void k_prededge(const float* __restrict__ P, const int* __restrict__ ei,
                           const float* __restrict__ bp1, const float* __restrict__ Wp2,
                           const float* __restrict__ bp2, float* __restrict__ out)
{
    int warp = (blockIdx.x * blockDim.x + threadIdx.x) >> 5;
    int lane = threadIdx.x & 31;
    int e0 = warp * 4;
    if (e0 >= N_EDGES_) return;

    float4 bv = ld4(&bp1[lane * 4]);
    float4 w2 = ld4(&Wp2[lane * 4]);
    float cc = bp2[0];

    #pragma unroll
    for (int n = 0; n < 4; n++) {
        int e = e0 + n;
        int src = ei[e];
        int dst = ei[N_EDGES_ + e];
        float4 a = ld4(&P[src * 256 + lane * 4]);
        float4 b = ld4(&P[dst * 256 + 128 + lane * 4]);
        float4 tt;
        tt.x = eluf(a.x + b.x + bv.x);
        tt.y = eluf(a.y + b.y + bv.y);
        tt.z = eluf(a.z + b.z + bv.z);
        tt.w = eluf(a.w + b.w + bv.w);
        float p = tt.x * w2.x + tt.y * w2.y + tt.z * w2.z + tt.w * w2.w;
        #pragma unroll
        for (int off = 16; off; off >>= 1)
            p += __shfl_xor_sync(0xffffffffu, p, off);
        if (lane == 0) out[e] = p + cc;
    }
}

// ---------------------------------------------------------------------------
extern "C" void kernel_launch(void* const* d_in, const int* in_sizes, int n_in,
                              void* d_out, int out_size)
{
    const float* x    = (const float*)d_in[0];
    const int*   ei   = (const int*)  d_in[1];
    const float* ea   = (const float*)d_in[2];
    const float* We0  = (const float*)d_in[3];
    const float* be0  = (const float*)d_in[4];
    const float* W10  = (const float*)d_in[5];
    const float* b10  = (const float*)d_in[6];
    const float* W20  = (const float*)d_in[7];
    const float* b20  = (const float*)d_in[8];
    const float* We_s = (const float*)d_in[9];
    const float* be_s = (const float*)d_in[10];
    const float* W1_s = (const float*)d_in[11];
    const float* b1_s = (const float*)d_in[12];
    const float* W2_s = (const float*)d_in[13];
    const float* b2_s = (const float*)d_in[14];
    const float* Wp1  = (const float*)d_in[15];
    const float* bp1  = (const float*)d_in[16];
    const float* Wp2  = (const float*)d_in[17];
    const float* bp2  = (const float*)d_in[18];
    float* out = (float*)d_out;

    float *hA, *hB, *P;
    uint4* WF;
    int *deg;
    cudaGetSymbolAddress((void**)&hA, g_h);
    cudaGetSymbolAddress((void**)&hB, g_hn);
    cudaGetSymbolAddress((void**)&P,  g_P);
    cudaGetSymbolAddress((void**)&WF, g_WF);
    cudaGetSymbolAddress((void**)&deg, g_deg);

    // ---- weight fragment prep + CSR build ----
    k_wfrag<<<(WF_TOTAL + 255) / 256, 256>>>(W10, W20, W1_s, W2_s, Wp1);
    cudaMemsetAsync(deg, 0, N_NODES_ * sizeof(int));
    k_hist <<<(N_EDGES_ + 255) / 256, 256>>>(ei);
    k_scanA<<<NBLK_, SCAN_B>>>();
    k_scanB<<<1, 128>>>();
    k_scanC<<<NBLK_, SCAN_B>>>();
    k_fill <<<(N_EDGES_ + 255) / 256, 256>>>(ei, ea);

    // ---- Layer 0 (16 -> 128) ----
    k_aggr0<<<(N_NODES_ * 16 + 255) / 256, 256>>>(x, We0, be0, P);   // reuse P as aggr16
    node_mlp16_tc<<<NODE_BLKS, 128>>>(x, P, b10, b20, hA);

    // ---- Layers 1..4 ----
    for (int l = 0; l < 4; l++) {
        gine_tc<<<NODE_BLKS, 128>>>(hA,
                                    We_s + l * HID_, be_s + l * HID_,
                                    WF + WF_W1 + l * 4096, b1_s + l * HID_,
                                    WF + WF_W2 + l * 4096, b2_s + l * HID_, hB);
        float* t = hA; hA = hB; hB = t;
    }

    // ---- Edge predictor ----
    k_prednode_tc<<<NODE_BLKS, 128>>>(hA, P);
    k_prededge<<<(N_EDGES_ / 4 * 32 + 255) / 256, 256>>>(P, ei, bp1, Wp2, bp2, out);
}

// round 13
// speedup vs baseline: 1.3047x; 1.3047x over previous
#include <cuda_runtime.h>
#include <math.h>

#define N_NODES_ 100000
#define N_EDGES_ 500000
#define HID_ 128
#define NIN_ 16
#define SCAN_B 1024
#define NBLK_ ((N_NODES_ + SCAN_B - 1) / SCAN_B)   // 98
#define NODE_BLKS ((N_NODES_ + 63) / 64)           // 1563
#define SSTR 132                                   // smem row stride (floats), conflict-free

typedef unsigned int uint32;

// ---- static scratch (no allocations allowed) ----
__device__ float g_h  [N_NODES_ * HID_];
__device__ float g_hn [N_NODES_ * HID_];
__device__ float g_P  [N_NODES_ * 2 * HID_];   // edge-pred node factors; reused as aggr16
__device__ int   g_deg   [N_NODES_];
__device__ int   g_incl  [N_NODES_];
__device__ int   g_rowptr[N_NODES_ + 1];
__device__ int   g_cursor[N_NODES_];
__device__ int   g_bsum  [NBLK_];
__device__ int   g_boff  [NBLK_];
__device__ int   g_csrc  [N_EDGES_];
__device__ float g_cea   [N_EDGES_];

// ---- fragment-ordered BF16 hi/lo weights: [kstep16][ntile][lane] = {bhi0,bhi1,blo0,blo1}
#define WF_W10 0                 // K=16 : 1*16*32   = 512
#define WF_W20 512               // K=128: 8*16*32   = 4096
#define WF_W1  4608              // 4 x 4096
#define WF_W2  20992             // 4 x 4096
#define WF_WPA 37376             // Wp1 rows 0..127
#define WF_WPB 41472             // Wp1 rows 128..255
#define WF_TOTAL 45568
__device__ uint4 g_WF[WF_TOTAL];

__device__ __forceinline__ float4 ld4(const float* p) { return *reinterpret_cast<const float4*>(p); }
__device__ __forceinline__ void st4(float* p, float4 v) { *reinterpret_cast<float4*>(p) = v; }
__device__ __forceinline__ float eluf(float x) { return x > 0.f ? x : expm1f(x); }

// ---- bf16 split helpers ----
// pack2(x0, x1): x0 -> low half, x1 -> high half (cvt d.hi = first src operand)
__device__ __forceinline__ uint32 pack2(float x0, float x1) {
    uint32 r; asm("cvt.rn.bf16x2.f32 %0, %1, %2;" : "=r"(r) : "f"(x1), "f"(x0)); return r;
}
__device__ __forceinline__ float lo_f(uint32 p) { return __uint_as_float(p << 16); }
__device__ __forceinline__ float hi_f(uint32 p) { return __uint_as_float(p & 0xffff0000u); }

// D += A(bf16) * B(bf16), m16n8k16
__device__ __forceinline__ void mma16(float c[4], uint32 a0, uint32 a1, uint32 a2, uint32 a3,
                                      uint32 b0, uint32 b1)
{
    asm volatile(
        "mma.sync.aligned.m16n8k16.row.col.f32.bf16.bf16.f32 "
        "{%0,%1,%2,%3}, {%4,%5,%6,%7}, {%8,%9}, {%0,%1,%2,%3};"
        : "+f"(c[0]), "+f"(c[1]), "+f"(c[2]), "+f"(c[3])
        : "r"(a0), "r"(a1), "r"(a2), "r"(a3), "r"(b0), "r"(b1));
}

// ---------------------------------------------------------------------------
// MMA phase body (shared by unroll variants)
// ---------------------------------------------------------------------------
__device__ __forceinline__ void mma_ks_body(const float* Zw, const uint4* __restrict__ WF,
                                            int ks, int g, int t, int lane, float c[16][4])
{
    int kb = ks * 16 + 2 * t;
    float2 za = *(const float2*)&Zw[g * SSTR + kb];
    float2 zb = *(const float2*)&Zw[(g + 8) * SSTR + kb];
    float2 zc = *(const float2*)&Zw[g * SSTR + kb + 8];
    float2 zd = *(const float2*)&Zw[(g + 8) * SSTR + kb + 8];
    uint32 ah0 = pack2(za.x, za.y);
    uint32 ah1 = pack2(zb.x, zb.y);
    uint32 ah2 = pack2(zc.x, zc.y);
    uint32 ah3 = pack2(zd.x, zd.y);
    uint32 al0 = pack2(za.x - lo_f(ah0), za.y - hi_f(ah0));
    uint32 al1 = pack2(zb.x - lo_f(ah1), zb.y - hi_f(ah1));
    uint32 al2 = pack2(zc.x - lo_f(ah2), zc.y - hi_f(ah2));
    uint32 al3 = pack2(zd.x - lo_f(ah3), zd.y - hi_f(ah3));
    const uint4* wrow = &WF[ks * 16 * 32 + lane];
    #pragma unroll
    for (int nt = 0; nt < 16; nt++) {
        uint4 wf = wrow[nt * 32];
        mma16(c[nt], ah0, ah1, ah2, ah3, wf.x, wf.y);   // Ahi*Bhi
        mma16(c[nt], al0, al1, al2, al3, wf.x, wf.y);   // Alo*Bhi
        mma16(c[nt], ah0, ah1, ah2, ah3, wf.z, wf.w);   // Ahi*Blo
    }
}

// MMA phase, minimal registers (unroll 1) — for gather-fused kernels
// where occupancy is critical. BYTE-IDENTICAL behavior to R11.
template <int KSTEPS16>
__device__ __forceinline__ void mma_phase(const float* Zw, const uint4* __restrict__ WF,
                                          int lane, float c[16][4])
{
    int g = lane >> 2, t = lane & 3;
    #pragma unroll
    for (int nt = 0; nt < 16; nt++) { c[nt][0] = 0.f; c[nt][1] = 0.f; c[nt][2] = 0.f; c[nt][3] = 0.f; }
    #pragma unroll 1
    for (int ks = 0; ks < KSTEPS16; ks++)
        mma_ks_body(Zw, WF, ks, g, t, lane, c);
}

// MMA phase, unroll 2 — for pure-MMA kernels (no gather) where a few extra
// registers are free and LDS latency at the loop top can be pipelined.
template <int KSTEPS16>
__device__ __forceinline__ void mma_phase_u2(const float* Zw, const uint4* __restrict__ WF,
                                             int lane, float c[16][4])
{
    int g = lane >> 2, t = lane & 3;
    #pragma unroll
    for (int nt = 0; nt < 16; nt++) { c[nt][0] = 0.f; c[nt][1] = 0.f; c[nt][2] = 0.f; c[nt][3] = 0.f; }
    #pragma unroll 2
    for (int ks = 0; ks < KSTEPS16; ks++)
        mma_ks_body(Zw, WF, ks, g, t, lane, c);
}

// ---------------------------------------------------------------------------
// Weight fragment prep (once per launch) + g_deg zeroing (fused memset)
// ---------------------------------------------------------------------------
#define PREP_N ((N_NODES_ + 255) & ~255)
__global__ void k_wfrag(const float* __restrict__ W10, const float* __restrict__ W20,
                        const float* __restrict__ W1s, const float* __restrict__ W2s,
                        const float* __restrict__ Wp1)
{
    int i = blockIdx.x * 256 + threadIdx.x;
    if (i < N_NODES_) g_deg[i] = 0;
    if (i >= WF_TOTAL) return;
    const float* W; int idx;
    if (i < 512)         { W = W10; idx = i; }
    else if (i < 4608)   { W = W20; idx = i - 512; }
    else if (i < 20992)  { int j = i - 4608;  W = W1s + (j >> 12) * 16384; idx = j & 4095; }
    else if (i < 37376)  { int j = i - 20992; W = W2s + (j >> 12) * 16384; idx = j & 4095; }
    else if (i < 41472)  { W = Wp1;           idx = i - 37376; }
    else                 { W = Wp1 + 16384;   idx = i - 41472; }
    int lane = idx & 31, nt = (idx >> 5) & 15, ks = idx >> 9;
    int t = lane & 3, g = lane >> 2;
    int n  = nt * 8 + g;
    int kb = ks * 16 + 2 * t;
    float w00 = W[kb * 128 + n];
    float w01 = W[(kb + 1) * 128 + n];
    float w10 = W[(kb + 8) * 128 + n];
    float w11 = W[(kb + 9) * 128 + n];
    uint32 h0 = pack2(w00, w01);
    uint32 h1 = pack2(w10, w11);
    uint32 l0 = pack2(w00 - lo_f(h0), w01 - hi_f(h0));
    uint32 l1 = pack2(w10 - lo_f(h1), w11 - hi_f(h1));
    g_WF[i] = make_uint4(h0, h1, l0, l1);
}

// ---------------------------------------------------------------------------
// CSR build (multi-block scan — verified fast path)
// ---------------------------------------------------------------------------
__global__ void k_hist(const int* __restrict__ ei) {
    int e = blockIdx.x * blockDim.x + threadIdx.x;
    if (e < N_EDGES_) atomicAdd(&g_deg[ei[N_EDGES_ + e]], 1);
}

__global__ void k_scanA() {
    __shared__ int s[SCAN_B];
    int t = threadIdx.x;
    int g = blockIdx.x * SCAN_B + t;
    int v = (g < N_NODES_) ? g_deg[g] : 0;
    s[t] = v; __syncthreads();
    for (int d = 1; d < SCAN_B; d <<= 1) {
        int u = (t >= d) ? s[t - d] : 0;
        __syncthreads(); s[t] += u; __syncthreads();
    }
    if (g < N_NODES_) g_incl[g] = s[t];
    if (t == SCAN_B - 1) g_bsum[blockIdx.x] = s[t];
}

__global__ void k_scanB() {
    __shared__ int s[128];
    int t = threadIdx.x;
    int v = (t < NBLK_) ? g_bsum[t] : 0;
    s[t] = v; __syncthreads();
    for (int d = 1; d < 128; d <<= 1) {
        int u = (t >= d) ? s[t - d] : 0;
        __syncthreads(); s[t] += u; __syncthreads();
    }
    if (t < NBLK_) g_boff[t] = s[t] - v;
}

__global__ void k_scanC() {
    int g = blockIdx.x * SCAN_B + threadIdx.x;
    if (g >= N_NODES_) return;
    int ex = g_incl[g] - g_deg[g] + g_boff[blockIdx.x];
    g_rowptr[g] = ex;
    g_cursor[g] = ex;
    if (g == N_NODES_ - 1) g_rowptr[N_NODES_] = g_incl[g] + g_boff[blockIdx.x];
}

__global__ void k_fill(const int* __restrict__ ei, const float* __restrict__ ea) {
    int e = blockIdx.x * blockDim.x + threadIdx.x;
    if (e >= N_EDGES_) return;
    int dst = ei[N_EDGES_ + e];
    int slot = atomicAdd(&g_cursor[dst], 1);
    g_csrc[slot] = ei[e];
    g_cea[slot]  = ea[e];
}

// ---------------------------------------------------------------------------
// Layer-0 aggregation (16 features) via CSR gather
// ---------------------------------------------------------------------------
__global__ void k_aggr0(const float* __restrict__ x, const float* __restrict__ We,
                        const float* __restrict__ be, float* __restrict__ aggr)
{
    int t = blockIdx.x * blockDim.x + threadIdx.x;
    int node = t >> 4;
    int f = t & 15;
    if (node >= N_NODES_) return;
    int beg = g_rowptr[node], end = g_rowptr[node + 1];
    float w = We[f], b = be[f], acc = 0.f;
    for (int p = beg; p < end; p++) {
        float m = x[g_csrc[p] * NIN_ + f] + g_cea[p] * w + b;
        acc += fmaxf(m, 0.f);
    }
    aggr[node * NIN_ + f] = acc;
}

// ---------------------------------------------------------------------------
// Layer-0 node MLP (tensor core): 64 nodes/block, 4 warps x 16 rows.
// No gather -> uses unroll-2 MMA for the K=128 phase.
// ---------------------------------------------------------------------------
__global__ void __launch_bounds__(128)
node_mlp16_tc(const float* __restrict__ xin, const float* __restrict__ aggr,
              const float* __restrict__ b1, const float* __restrict__ b2,
              float* __restrict__ hout)
{
    __shared__ __align__(16) float Z[64 * SSTR];

    int tid = threadIdx.x, w = tid >> 5, lane = tid & 31;
    int nb = blockIdx.x * 64;

    for (int i = tid; i < 64 * 4; i += 128) {
        int row = i >> 2, c4 = i & 3;
        int node = nb + row;
        float4 v = make_float4(0.f, 0.f, 0.f, 0.f);
        if (node < N_NODES_) {
            float4 a = ld4(&xin[node * NIN_ + c4 * 4]);
            float4 g = ld4(&aggr[node * NIN_ + c4 * 4]);
            v = make_float4(a.x + g.x, a.y + g.y, a.z + g.z, a.w + g.w);
        }
        st4(&Z[row * SSTR + c4 * 4], v);
    }
    __syncthreads();

    float c[16][4];
    const float* Zw = &Z[w * 16 * SSTR];
    int g = lane >> 2, t = lane & 3;

    mma_phase<1>(Zw, &g_WF[WF_W10], lane, c);
    __syncwarp();
    #pragma unroll
    for (int nt = 0; nt < 16; nt++) {
        int col = nt * 8 + 2 * t;
        float2 bb = *(const float2*)&b1[col];
        float2 e0 = make_float2(eluf(c[nt][0] + bb.x), eluf(c[nt][1] + bb.y));
        float2 e1 = make_float2(eluf(c[nt][2] + bb.x), eluf(c[nt][3] + bb.y));
        *(float2*)&Z[(w * 16 + g) * SSTR + col]     = e0;
        *(float2*)&Z[(w * 16 + g + 8) * SSTR + col] = e1;
    }
    __syncwarp();

    mma_phase_u2<8>(Zw, &g_WF[WF_W20], lane, c);
    int n0 = nb + w * 16 + g;
    #pragma unroll
    for (int nt = 0; nt < 16; nt++) {
        int col = nt * 8 + 2 * t;
        float2 bb = *(const float2*)&b2[col];
        float2 e0 = make_float2(eluf(c[nt][0] + bb.x), eluf(c[nt][1] + bb.y));
        float2 e1 = make_float2(eluf(c[nt][2] + bb.x), eluf(c[nt][3] + bb.y));
        if (n0 < N_NODES_)     *(float2*)&hout[n0 * HID_ + col]       = e0;
        if (n0 + 8 < N_NODES_) *(float2*)&hout[(n0 + 8) * HID_ + col] = e1;
    }
}

// ---------------------------------------------------------------------------
// Fused GINE layer: CSR gather + 2 MMA phases. BYTE-IDENTICAL to R11
// (occupancy-critical: no register-count changes allowed here).
// ---------------------------------------------------------------------------
__global__ void __launch_bounds__(128)
gine_tc(const float* __restrict__ h,
        const float* __restrict__ We, const float* __restrict__ be,
        const uint4* __restrict__ WF1, const float* __restrict__ b1,
        const uint4* __restrict__ WF2, const float* __restrict__ b2,
        float* __restrict__ hout)
{
    __shared__ __align__(16) float Z[64 * SSTR];

    int tid = threadIdx.x, w = tid >> 5, lane = tid & 31;
    int nb = blockIdx.x * 64;

    // gather prologue: each warp fills its 16 rows
    {
        float4 wv = ld4(&We[lane * 4]);
        float4 bg = ld4(&be[lane * 4]);
        for (int n = 0; n < 16; n++) {
            int node = nb + w * 16 + n;
            float4 acc = make_float4(0.f, 0.f, 0.f, 0.f);
            if (node < N_NODES_) {
                acc = ld4(&h[node * HID_ + lane * 4]);
                int beg = g_rowptr[node], end = g_rowptr[node + 1];
                for (int p = beg; p < end; p++) {
                    int s = g_csrc[p];
                    float we = g_cea[p];
                    float4 hv = ld4(&h[s * HID_ + lane * 4]);
                    acc.x += fmaxf(fmaf(we, wv.x, hv.x) + bg.x, 0.f);
                    acc.y += fmaxf(fmaf(we, wv.y, hv.y) + bg.y, 0.f);
                    acc.z += fmaxf(fmaf(we, wv.z, hv.z) + bg.z, 0.f);
                    acc.w += fmaxf(fmaf(we, wv.w, hv.w) + bg.w, 0.f);
                }
            }
            st4(&Z[(w * 16 + n) * SSTR + lane * 4], acc);
        }
    }
    __syncwarp();

    float c[16][4];
    const float* Zw = &Z[w * 16 * SSTR];
    int g = lane >> 2, t = lane & 3;

    mma_phase<8>(Zw, WF1, lane, c);
    __syncwarp();
    #pragma unroll
    for (int nt = 0; nt < 16; nt++) {
        int col = nt * 8 + 2 * t;
        float2 bb = *(const float2*)&b1[col];
        float2 e0 = make_float2(eluf(c[nt][0] + bb.x), eluf(c[nt][1] + bb.y));
        float2 e1 = make_float2(eluf(c[nt][2] + bb.x), eluf(c[nt][3] + bb.y));
        *(float2*)&Z[(w * 16 + g) * SSTR + col]     = e0;
        *(float2*)&Z[(w * 16 + g + 8) * SSTR + col] = e1;
    }
    __syncwarp();

    mma_phase<8>(Zw, WF2, lane, c);
    int n0 = nb + w * 16 + g;
    #pragma unroll
    for (int nt = 0; nt < 16; nt++) {
        int col = nt * 8 + 2 * t;
        float2 bb = *(const float2*)&b2[col];
        float2 e0 = make_float2(eluf(c[nt][0] + bb.x), eluf(c[nt][1] + bb.y));
        float2 e1 = make_float2(eluf(c[nt][2] + bb.x), eluf(c[nt][3] + bb.y));
        if (n0 < N_NODES_)     *(float2*)&hout[n0 * HID_ + col]       = e0;
        if (n0 + 8 < N_NODES_) *(float2*)&hout[(n0 + 8) * HID_ + col] = e1;
    }
}

// ---------------------------------------------------------------------------
// Edge-predictor node factors. Pure MMA -> unroll-2 phases.
// ---------------------------------------------------------------------------
__global__ void __launch_bounds__(128)
k_prednode_tc(const float* __restrict__ h, float* __restrict__ P)
{
    __shared__ __align__(16) float Z[64 * SSTR];

    int tid = threadIdx.x, w = tid >> 5, lane = tid & 31;
    int nb = blockIdx.x * 64;

    for (int i = tid; i < 64 * 32; i += 128) {
        int row = i >> 5, c4 = i & 31;
        int node = nb + row;
        float4 v = make_float4(0.f, 0.f, 0.f, 0.f);
        if (node < N_NODES_) v = ld4(&h[node * HID_ + c4 * 4]);
        st4(&Z[row * SSTR + c4 * 4], v);
    }
    __syncthreads();

    float c[16][4];
    const float* Zw = &Z[w * 16 * SSTR];
    int g = lane >> 2, t = lane & 3;
    int n0 = nb + w * 16 + g;

    mma_phase_u2<8>(Zw, &g_WF[WF_WPA], lane, c);
    #pragma unroll
    for (int nt = 0; nt < 16; nt++) {
        int col = nt * 8 + 2 * t;
        if (n0 < N_NODES_)     *(float2*)&P[n0 * 256 + col]       = make_float2(c[nt][0], c[nt][1]);
        if (n0 + 8 < N_NODES_) *(float2*)&P[(n0 + 8) * 256 + col] = make_float2(c[nt][2], c[nt][3]);
    }

    mma_phase_u2<8>(Zw, &g_WF[WF_WPB], lane, c);
    #pragma unroll
    for (int nt = 0; nt < 16; nt++) {
        int col = nt * 8 + 2 * t;
        if (n0 < N_NODES_)     *(float2*)&P[n0 * 256 + 128 + col]       = make_float2(c[nt][0], c[nt][1]);
        if (n0 + 8 < N_NODES_) *(float2*)&P[(n0 + 8) * 256 + 128 + col] = make_float2(c[nt][2], c[nt][3]);
    }
}

// ---------------------------------------------------------------------------
// Per-edge predictor epilogue: out[e] = elu(A[src]+B[dst]+bp1) . Wp2 + bp2
// ---------------------------------------------------------------------------
__global__ void k_prededge(const float* __restrict__ P, const int* __restrict__ ei,
                           const float* __restrict__ bp1, const float* __restrict__ Wp2,
                           const float* __restrict__ bp2, float* __restrict__ out)
{
    int warp = (blockIdx.x * blockDim.x + threadIdx.x) >> 5;
    int lane = threadIdx.x & 31;
    int e0 = warp * 4;
    if (e0 >= N_EDGES_) return;

    float4 bv = ld4(&bp1[lane * 4]);
    float4 w2 = ld4(&Wp2[lane * 4]);
    float cc = bp2[0];

    #pragma unroll
    for (int n = 0; n < 4; n++) {
        int e = e0 + n;
        int src = ei[e];
        int dst = ei[N_EDGES_ + e];
        float4 a = ld4(&P[src * 256 + lane * 4]);
        float4 b = ld4(&P[dst * 256 + 128 + lane * 4]);
        float4 tt;
        tt.x = eluf(a.x + b.x + bv.x);
        tt.y = eluf(a.y + b.y + bv.y);
        tt.z = eluf(a.z + b.z + bv.z);
        tt.w = eluf(a.w + b.w + bv.w);
        float p = tt.x * w2.x + tt.y * w2.y + tt.z * w2.z + tt.w * w2.w;
        #pragma unroll
        for (int off = 16; off; off >>= 1)
            p += __shfl_xor_sync(0xffffffffu, p, off);
        if (lane == 0) out[e] = p + cc;
    }
}

// ---------------------------------------------------------------------------
extern "C" void kernel_launch(void* const* d_in, const int* in_sizes, int n_in,
                              void* d_out, int out_size)
{
    const float* x    = (const float*)d_in[0];
    const int*   ei   = (const int*)  d_in[1];
    const float* ea   = (const float*)d_in[2];
    const float* We0  = (const float*)d_in[3];
    const float* be0  = (const float*)d_in[4];
    const float* W10  = (const float*)d_in[5];
    const float* b10  = (const float*)d_in[6];
    const float* W20  = (const float*)d_in[7];
    const float* b20  = (const float*)d_in[8];
    const float* We_s = (const float*)d_in[9];
    const float* be_s = (const float*)d_in[10];
    const float* W1_s = (const float*)d_in[11];
    const float* b1_s = (const float*)d_in[12];
    const float* W2_s = (const float*)d_in[13];
    const float* b2_s = (const float*)d_in[14];
    const float* Wp1  = (const float*)d_in[15];
    const float* bp1  = (const float*)d_in[16];
    const float* Wp2  = (const float*)d_in[17];
    const float* bp2  = (const float*)d_in[18];
    float* out = (float*)d_out;

    float *hA, *hB, *P;
    uint4* WF;
    cudaGetSymbolAddress((void**)&hA, g_h);
    cudaGetSymbolAddress((void**)&hB, g_hn);
    cudaGetSymbolAddress((void**)&P,  g_P);
    cudaGetSymbolAddress((void**)&WF, g_WF);

    // ---- weight fragment prep (incl. deg zeroing) + CSR build ----
    k_wfrag<<<PREP_N / 256, 256>>>(W10, W20, W1_s, W2_s, Wp1);
    k_hist <<<(N_EDGES_ + 255) / 256, 256>>>(ei);
    k_scanA<<<NBLK_, SCAN_B>>>();
    k_scanB<<<1, 128>>>();
    k_scanC<<<NBLK_, SCAN_B>>>();
    k_fill <<<(N_EDGES_ + 255) / 256, 256>>>(ei, ea);

    // ---- Layer 0 (16 -> 128) ----
    k_aggr0<<<(N_NODES_ * 16 + 255) / 256, 256>>>(x, We0, be0, P);   // reuse P as aggr16
    node_mlp16_tc<<<NODE_BLKS, 128>>>(x, P, b10, b20, hA);

    // ---- Layers 1..4 ----
    for (int l = 0; l < 4; l++) {
        gine_tc<<<NODE_BLKS, 128>>>(hA,
                                    We_s + l * HID_, be_s + l * HID_,
                                    WF + WF_W1 + l * 4096, b1_s + l * HID_,
                                    WF + WF_W2 + l * 4096, b2_s + l * HID_, hB);
        float* t = hA; hA = hB; hB = t;
    }

    // ---- Edge predictor ----
    k_prednode_tc<<<NODE_BLKS, 128>>>(hA, P);
    k_prededge<<<(N_EDGES_ / 4 * 32 + 255) / 256, 256>>>(P, ei, bp1, Wp2, bp2, out);
}